// round 6
// baseline (speedup 1.0000x reference)
#include <cuda_runtime.h>
#include <cuda_bf16.h>

#define NN 100000
#define EE 1600000

__device__ float4 g_t[NN * 8];     // ts = (h @ W) * dinv[row]
__device__ float4 g_agg[NN * 8];   // scatter accumulator / h in place
__device__ float  g_dinv[NN];

// zero accumulator + set deg = 1 (self loop)
__global__ void k_init(int n) {
    int i = blockIdx.x * blockDim.x + threadIdx.x;
    if (i < n * 8) g_agg[i] = make_float4(0.f, 0.f, 0.f, 0.f);
    if (i < n) g_dinv[i] = 1.0f;
}

// zero accumulator only (layer 2 — must NOT touch dinv)
__global__ void k_zero(int n) {
    int i = blockIdx.x * blockDim.x + threadIdx.x;
    if (i < n * 8) g_agg[i] = make_float4(0.f, 0.f, 0.f, 0.f);
}

__global__ void k_deg(const int* __restrict__ dst, int E) {
    int e = blockIdx.x * blockDim.x + threadIdx.x;
    if (e < E) atomicAdd(&g_dinv[dst[e]], 1.0f);
}

__global__ void k_rsqrt(int n) {
    int i = blockIdx.x * blockDim.x + threadIdx.x;
    if (i < n) g_dinv[i] = rsqrtf(g_dinv[i]);
}

// T[row] = (X[row] @ W) * dinv[row]; packed fma.rn.f32x2.
// X == nullptr  =>  read input rows from g_agg (device-side symbol — the
// host must NEVER pass the address of a __device__ global).
__global__ void k_gemm(const float4* __restrict__ X,
                       const float* __restrict__ Wa,
                       const float* __restrict__ Wb,
                       int n) {
    __shared__ unsigned long long Ws[32][16];
    int tid = threadIdx.x;
    for (int idx = tid; idx < 512; idx += blockDim.x) {
        int k  = idx >> 4;
        int cp = idx & 15;
        int c0 = cp * 2;
        float v0, v1;
        if (Wb == nullptr) {           // layer 1: W1 [32x32]
            v0 = Wa[k * 32 + c0];
            v1 = Wa[k * 32 + c0 + 1];
        } else if (c0 < 16) {          // layer 2 cols 0-15: Wmu [32x16]
            v0 = Wa[k * 16 + c0];
            v1 = Wa[k * 16 + c0 + 1];
        } else {                       // layer 2 cols 16-31: Wlv [32x16]
            v0 = Wb[k * 16 + (c0 - 16)];
            v1 = Wb[k * 16 + (c0 - 15)];
        }
        unsigned long long p;
        asm("mov.b64 %0, {%1,%2};" : "=l"(p) : "f"(v0), "f"(v1));
        Ws[k][cp] = p;
    }
    __syncthreads();

    int row = blockIdx.x * blockDim.x + tid;
    if (row >= n) return;

    const float4* xr = (X != nullptr) ? (X + (size_t)row * 8)
                                      : (g_agg + (size_t)row * 8);
    float x[32];
#pragma unroll
    for (int q = 0; q < 8; q++) {
        float4 v = xr[q];
        x[4 * q + 0] = v.x; x[4 * q + 1] = v.y;
        x[4 * q + 2] = v.z; x[4 * q + 3] = v.w;
    }

    unsigned long long acc[16];
#pragma unroll
    for (int cp = 0; cp < 16; cp++) acc[cp] = 0ull;

#pragma unroll
    for (int k = 0; k < 32; k++) {
        unsigned long long xk;
        asm("mov.b64 %0, {%1,%1};" : "=l"(xk) : "f"(x[k]));
#pragma unroll
        for (int cp = 0; cp < 16; cp++) {
            asm("fma.rn.f32x2 %0, %1, %2, %0;"
                : "+l"(acc[cp]) : "l"(xk), "l"(Ws[k][cp]));
        }
    }

    float di = g_dinv[row];
    unsigned long long d2;
    asm("mov.b64 %0, {%1,%1};" : "=l"(d2) : "f"(di));

    float o[32];
#pragma unroll
    for (int cp = 0; cp < 16; cp++) {
        asm("mul.rn.f32x2 %0, %0, %1;" : "+l"(acc[cp]) : "l"(d2));
        asm("mov.b64 {%0,%1}, %2;"
            : "=f"(o[2 * cp]), "=f"(o[2 * cp + 1]) : "l"(acc[cp]));
    }

    float4* tr = g_t + (size_t)row * 8;
#pragma unroll
    for (int q = 0; q < 8; q++)
        tr[q] = make_float4(o[4 * q], o[4 * q + 1], o[4 * q + 2], o[4 * q + 3]);
}

// AGG[dst] += T[src]; 8 threads/edge; float4 gather + vector reduction
__global__ void k_scatter(const int* __restrict__ src,
                          const int* __restrict__ dst, int E) {
    int gid = blockIdx.x * blockDim.x + threadIdx.x;
    int e = gid >> 3;
    if (e >= E) return;
    int c = gid & 7;
    int s = __ldg(&src[e]);
    int d = __ldg(&dst[e]);
    float4 v = g_t[(size_t)s * 8 + c];
    float4* p = g_agg + (size_t)d * 8 + c;
    asm volatile("red.global.add.v4.f32 [%0], {%1,%2,%3,%4};"
                 :: "l"(p), "f"(v.x), "f"(v.y), "f"(v.z), "f"(v.w)
                 : "memory");
}

// h = relu(dinv * (agg + ts) + b1), in place into g_agg
__global__ void k_post1(const float* __restrict__ b, int n) {
    int gid = blockIdx.x * blockDim.x + threadIdx.x;
    int i = gid >> 3;
    if (i >= n) return;
    int c = gid & 7;
    float di = g_dinv[i];
    float4 a = g_agg[(size_t)i * 8 + c];
    float4 t = g_t[(size_t)i * 8 + c];
    float4 bb = ((const float4*)b)[c];
    float4 r;
    r.x = fmaxf(fmaf(di, a.x + t.x, bb.x), 0.f);
    r.y = fmaxf(fmaf(di, a.y + t.y, bb.y), 0.f);
    r.z = fmaxf(fmaf(di, a.z + t.z, bb.z), 0.f);
    r.w = fmaxf(fmaf(di, a.w + t.w, bb.w), 0.f);
    g_agg[(size_t)i * 8 + c] = r;
}

// mu -> out[0:N*16], logvar -> out[N*16:]
__global__ void k_post2(const float* __restrict__ bmu,
                        const float* __restrict__ blv,
                        float* __restrict__ out, int n) {
    int gid = blockIdx.x * blockDim.x + threadIdx.x;
    int i = gid >> 3;
    if (i >= n) return;
    int c = gid & 7;
    float di = g_dinv[i];
    float4 a = g_agg[(size_t)i * 8 + c];
    float4 t = g_t[(size_t)i * 8 + c];
    float4 r;
    if (c < 4) {
        float4 bb = ((const float4*)bmu)[c];
        r.x = fmaf(di, a.x + t.x, bb.x);
        r.y = fmaf(di, a.y + t.y, bb.y);
        r.z = fmaf(di, a.z + t.z, bb.z);
        r.w = fmaf(di, a.w + t.w, bb.w);
        ((float4*)out)[(size_t)i * 4 + c] = r;
    } else {
        float4 bb = ((const float4*)blv)[c - 4];
        r.x = fmaf(di, a.x + t.x, bb.x);
        r.y = fmaf(di, a.y + t.y, bb.y);
        r.z = fmaf(di, a.z + t.z, bb.z);
        r.w = fmaf(di, a.w + t.w, bb.w);
        ((float4*)(out + (size_t)n * 16))[(size_t)i * 4 + (c - 4)] = r;
    }
}

extern "C" void kernel_launch(void* const* d_in, const int* in_sizes, int n_in,
                              void* d_out, int out_size) {
    const float* x   = (const float*)d_in[0];
    const int*   ei  = (const int*)d_in[1];
    const float* W1  = (const float*)d_in[2];
    const float* b1  = (const float*)d_in[3];
    const float* Wmu = (const float*)d_in[4];
    const float* bmu = (const float*)d_in[5];
    const float* Wlv = (const float*)d_in[6];
    const float* blv = (const float*)d_in[7];
    float* out = (float*)d_out;

    int N = in_sizes[0] / 32;
    int E = in_sizes[1] / 2;
    const int* src = ei;          // edge_index row 0
    const int* dst = ei + E;      // edge_index row 1

    const int TB = 256;
    int gN8 = (N * 8 + TB - 1) / TB;
    int gN  = (N + TB - 1) / TB;
    int gE  = (E + TB - 1) / TB;
    int gE8 = (int)(((long long)E * 8 + TB - 1) / TB);

    // degree / dinv (+ zero accumulator for layer 1)
    k_init<<<gN8, TB>>>(N);
    k_deg<<<gE, TB>>>(dst, E);
    k_rsqrt<<<gN, TB>>>(N);

    // layer 1
    k_gemm<<<gN, TB>>>((const float4*)x, W1, nullptr, N);
    k_scatter<<<gE8, TB>>>(src, dst, E);
    k_post1<<<gN8, TB>>>(b1, N);                 // h in g_agg

    // layer 2: mu|logvar fused into one 32-col scatter.
    // X = nullptr  =>  kernel reads h from g_agg via the DEVICE-side symbol
    // (host-side &g_agg is the shadow symbol — that was the round-4 bug).
    k_gemm<<<gN, TB>>>(nullptr, Wmu, Wlv, N);
    k_zero<<<gN8, TB>>>(N);                      // zero accumulator only
    k_scatter<<<gE8, TB>>>(src, dst, E);
    k_post2<<<gN8, TB>>>(bmu, blv, out, N);
}